// round 2
// baseline (speedup 1.0000x reference)
#include <cuda_runtime.h>
#include <cuda_bf16.h>

// Problem constants (fixed shapes from reference setup_inputs)
#define HH 512
#define WW 640
#define RAD 4          // K=9 -> R=4
#define EPS_C 0.5f

#define BX 32
#define BY 16
#define SW (BX + 2*RAD)   // 40
#define SH (BY + RAD)     // 20 (only dh >= 0 needed: half-space symmetry)

__device__ double g_acc;

__global__ void init_acc_kernel() { g_acc = 0.0; }

// ---------------------------------------------------------------------------
// Kernel 1: pattern_proj[b,v,u] = bilinear(pattern[v,:], x = clamp(u - disp, 0, W-1))
// ---------------------------------------------------------------------------
__global__ void proj_kernel(const float* __restrict__ disp,
                            const float* __restrict__ pattern,
                            float* __restrict__ proj, int total)
{
    for (int idx = blockIdx.x * blockDim.x + threadIdx.x; idx < total;
         idx += gridDim.x * blockDim.x) {
        int u = idx % WW;
        int v = (idx / WW) % HH;
        float d = disp[idx];
        float x = (float)u - d;
        x = fminf(fmaxf(x, 0.0f), (float)(WW - 1));
        float xf = floorf(x);
        float w  = x - xf;
        int i0 = (int)xf;
        int i1 = min(i0 + 1, WW - 1);
        const float* prow = pattern + v * WW;
        float g0 = __ldg(prow + i0);
        float g1 = __ldg(prow + i1);
        proj[idx] = fmaf(w, g1 - g0, g0);
    }
}

// ---------------------------------------------------------------------------
// Kernel 2: census-SAD partial sum over half-space offsets (dh>0, or dh==0 && dw>0).
// Each unordered neighbor pair is counted once; final value doubled at the end.
// ---------------------------------------------------------------------------
template<bool INTERIOR>
__device__ __forceinline__ float census_accum(
    const float (&As)[SH][SW], const float (&Bs)[SH][SW],
    int tx, int ty, int gx, int gy)
{
    float ac = As[ty][tx + RAD];
    float bc = Bs[ty][tx + RAD];
    float acc = 0.f;
#pragma unroll
    for (int dh = 0; dh <= RAD; dh++) {
#pragma unroll
        for (int dw = -RAD; dw <= RAD; dw++) {
            if (dh == 0 && dw <= 0) continue;  // half-space only
            float na = As[ty + dh][tx + RAD + dw];
            float nb = Bs[ty + dh][tx + RAD + dw];
            float da = na - ac;
            float db = nb - bc;
            float ca = __fdividef(da, EPS_C + fabsf(da));
            float cb = __fdividef(db, EPS_C + fabsf(db));
            float t = fabsf(ca - cb);
            if (!INTERIOR) {
                bool valid = (gy + dh < HH) && (gx + dw >= 0) && (gx + dw < WW);
                t = valid ? t : 0.f;
            }
            acc += t;
        }
    }
    return acc;
}

__global__ __launch_bounds__(BX * BY)
void census_kernel(const float* __restrict__ a_g,   // pattern_proj
                   const float* __restrict__ b_g)   // im
{
    __shared__ float As[SH][SW];
    __shared__ float Bs[SH][SW];

    int bimg = blockIdx.z;
    int x0 = blockIdx.x * BX;
    int y0 = blockIdx.y * BY;
    const float* ap = a_g + (size_t)bimg * (HH * WW);
    const float* bp = b_g + (size_t)bimg * (HH * WW);

    int tid = threadIdx.y * BX + threadIdx.x;

    bool interior = (x0 >= RAD) && (x0 + BX + RAD <= WW) && (y0 + BY + RAD <= HH);

    // cooperative tile load (rows y0..y0+SH-1, cols x0-RAD..x0+BX+RAD-1)
    for (int i = tid; i < SH * SW; i += BX * BY) {
        int sy = i / SW, sx = i % SW;
        int gy = y0 + sy;
        int gx = x0 + sx - RAD;
        float av = 0.f, bv = 0.f;
        if (interior || (gy < HH && gx >= 0 && gx < WW)) {
            int g = gy * WW + gx;
            av = ap[g];
            bv = bp[g];
        }
        As[sy][sx] = av;
        Bs[sy][sx] = bv;
    }
    __syncthreads();

    int tx = threadIdx.x, ty = threadIdx.y;
    int gx = x0 + tx, gy = y0 + ty;

    float acc = interior ? census_accum<true >(As, Bs, tx, ty, gx, gy)
                         : census_accum<false>(As, Bs, tx, ty, gx, gy);

    // block reduce -> one double atomic per block
#pragma unroll
    for (int o = 16; o > 0; o >>= 1)
        acc += __shfl_down_sync(0xffffffffu, acc, o);

    __shared__ float warpsum[BX * BY / 32];
    if ((tid & 31) == 0) warpsum[tid >> 5] = acc;
    __syncthreads();
    if (tid < (BX * BY / 32)) {
        float s = warpsum[tid];
#pragma unroll
        for (int o = (BX * BY / 64); o > 0; o >>= 1)
            s += __shfl_down_sync(0xffffffffu, s, o);
        if (tid == 0) atomicAdd(&g_acc, (double)s);
    }
}

// ---------------------------------------------------------------------------
// Kernel 3: finalize scalar. val = 2 * g_acc / (81 * B*H*W)
// ---------------------------------------------------------------------------
__global__ void finalize_kernel(float* __restrict__ out, int lead, double inv_norm)
{
    float v = (float)(2.0 * g_acc * inv_norm);
    for (int i = 0; i < lead; i++) out[i] = v;
}

extern "C" void kernel_launch(void* const* d_in, const int* in_sizes, int n_in,
                              void* d_out, int out_size)
{
    const float* disp    = (const float*)d_in[0];
    const float* im      = (const float*)d_in[1];
    const float* pattern = (const float*)d_in[2];
    float* out = (float*)d_out;

    int total = in_sizes[0];            // B*1*H*W
    int B = total / (HH * WW);
    int lead = out_size - total;        // scalar(s) precede pattern_proj in output
    float* proj = out + lead;

    init_acc_kernel<<<1, 1>>>();

    int nblk = (total + 511) / 512;
    if (nblk > 4096) nblk = 4096;
    proj_kernel<<<nblk, 512>>>(disp, pattern, proj, total);

    dim3 grid(WW / BX, HH / BY, B);
    dim3 blk(BX, BY);
    census_kernel<<<grid, blk>>>(proj, im);

    finalize_kernel<<<1, 1>>>(out, lead, 1.0 / (81.0 * (double)total));
}

// round 3
// speedup vs baseline: 1.0991x; 1.0991x over previous
#include <cuda_runtime.h>
#include <cuda_bf16.h>

// Fixed problem shapes
#define HH 512
#define WW 640
#define RAD 4             // K=9 -> R=4
#define EPS_C 0.5f

// Census tile config: 32x8 threads, 4 pixels per thread -> 128x8 pixel tile
#define BXT 32
#define BYT 8
#define PX  4
#define TILE_W (BXT*PX)         // 128
#define TW (TILE_W + 2*RAD)     // 136 floats per halo row
#define TH (BYT + RAD)          // 12 halo rows (dh >= 0 only)
#define NTHREADS (BXT*BYT)      // 256

__device__ double g_acc;

// ---------------------------------------------------------------------------
// Packed f32x2 helpers (sm_100a)
// ---------------------------------------------------------------------------
union PU { float2 f; unsigned long long u; };

__device__ __forceinline__ float2 padd(float2 a, float2 b) {
    PU x, y, r; x.f = a; y.f = b;
    asm("add.rn.f32x2 %0,%1,%2;" : "=l"(r.u) : "l"(x.u), "l"(y.u));
    return r.f;
}
__device__ __forceinline__ float2 psub(float2 a, float2 b) {
    PU x, y, r; x.f = a; y.f = b;
    asm("sub.rn.f32x2 %0,%1,%2;" : "=l"(r.u) : "l"(x.u), "l"(y.u));
    return r.f;
}
__device__ __forceinline__ float2 pmul(float2 a, float2 b) {
    PU x, y, r; x.f = a; y.f = b;
    asm("mul.rn.f32x2 %0,%1,%2;" : "=l"(r.u) : "l"(x.u), "l"(y.u));
    return r.f;
}
__device__ __forceinline__ float2 pabs(float2 a) {
    PU x; x.f = a; x.u &= 0x7FFFFFFF7FFFFFFFULL; return x.f;
}
__device__ __forceinline__ float frcp(float x) {
    float r; asm("rcp.approx.ftz.f32 %0,%1;" : "=f"(r) : "f"(x)); return r;
}

// ---------------------------------------------------------------------------
// Kernel 1: pattern_proj + zero the global accumulator
// ---------------------------------------------------------------------------
__global__ void proj_kernel(const float* __restrict__ disp,
                            const float* __restrict__ pattern,
                            float* __restrict__ proj, int total)
{
    int idx = blockIdx.x * blockDim.x + threadIdx.x;
    if (idx == 0) g_acc = 0.0;       // census runs after this kernel completes
    if (idx >= total) return;
    int u = idx % WW;
    int v = (idx / WW) % HH;
    float d = disp[idx];
    float x = (float)u - d;
    x = fminf(fmaxf(x, 0.0f), (float)(WW - 1));
    float xf = floorf(x);
    float w  = x - xf;
    int i0 = (int)xf;
    int i1 = min(i0 + 1, WW - 1);
    const float* prow = pattern + v * WW;
    float g0 = __ldg(prow + i0);
    float g1 = __ldg(prow + i1);
    proj[idx] = fmaf(w, g1 - g0, g0);
}

// ---------------------------------------------------------------------------
// Census pair op: two pixel-pairs packed. Single reciprocal per pair:
//   |ca - cb| = |da*sb - db*sa| / (sa*sb),  sa = eps+|da|, sb = eps+|db|
// ---------------------------------------------------------------------------
template<bool CM>
__device__ __forceinline__ void census_pair(float2 na, float2 nb,
                                            float2 ac, float2 bc,
                                            float2 m, float2& acc)
{
    const float2 eps2 = {EPS_C, EPS_C};
    float2 da = psub(na, ac);
    float2 db = psub(nb, bc);
    float2 sa = padd(eps2, pabs(da));
    float2 sb = padd(eps2, pabs(db));
    float2 p  = pmul(da, sb);
    float2 q  = pmul(db, sa);
    float2 num = pabs(psub(p, q));
    float2 den = pmul(sa, sb);
    float r0 = frcp(den.x);
    float r1 = frcp(den.y);
    if (CM) { r0 *= m.x; r1 *= m.y; }
    acc.x = fmaf(num.x, r0, acc.x);
    acc.y = fmaf(num.y, r1, acc.y);
}

// Process one dh row: neighbors for dw = JLO-4 .. 4, pixels px0..px3.
// Row data comes packed at both parities: E pairs from base arrays,
// O pairs from the 1-float-shifted copies.
template<int JLO, bool CM>
__device__ __forceinline__ void row_accum(
    const float* __restrict__ As_row, const float* __restrict__ A1_row,
    const float* __restrict__ Bs_row, const float* __restrict__ B1_row,
    int cb,
    float2 ac01, float2 ac23, float2 bc01, float2 bc23,
    const float2 (&m01)[9], const float2 (&m23)[9],
    float2& acc01, float2& acc23)
{
    const float4* pa  = (const float4*)(As_row + cb);
    const float4* pa1 = (const float4*)(A1_row + cb);
    const float4* pb  = (const float4*)(Bs_row + cb);
    const float4* pb1 = (const float4*)(B1_row + cb);
    float4 ea0 = pa[0],  ea1 = pa[1],  ea2 = pa[2];
    float4 oa0 = pa1[0], oa1 = pa1[1], oa2 = pa1[2];
    float4 eb0 = pb[0],  eb1 = pb[1],  eb2 = pb[2];
    float4 ob0 = pb1[0], ob1 = pb1[1], ob2 = pb1[2];

    float2 EA[6] = {{ea0.x,ea0.y},{ea0.z,ea0.w},{ea1.x,ea1.y},{ea1.z,ea1.w},{ea2.x,ea2.y},{ea2.z,ea2.w}};
    float2 OA[6] = {{oa0.x,oa0.y},{oa0.z,oa0.w},{oa1.x,oa1.y},{oa1.z,oa1.w},{oa2.x,oa2.y},{oa2.z,oa2.w}};
    float2 EB[6] = {{eb0.x,eb0.y},{eb0.z,eb0.w},{eb1.x,eb1.y},{eb1.z,eb1.w},{eb2.x,eb2.y},{eb2.z,eb2.w}};
    float2 OB[6] = {{ob0.x,ob0.y},{ob0.z,ob0.w},{ob1.x,ob1.y},{ob1.z,ob1.w},{ob2.x,ob2.y},{ob2.z,ob2.w}};

#pragma unroll
    for (int j = JLO; j < 9; j++) {
        // pair start column (halo-relative, minus cb): px01 -> s=j, px23 -> s=j+2
        const int s01 = j;
        const int s23 = j + 2;
        float2 na01 = (s01 & 1) ? OA[(s01-1) >> 1] : EA[s01 >> 1];
        float2 nb01 = (s01 & 1) ? OB[(s01-1) >> 1] : EB[s01 >> 1];
        float2 na23 = (s23 & 1) ? OA[(s23-1) >> 1] : EA[s23 >> 1];
        float2 nb23 = (s23 & 1) ? OB[(s23-1) >> 1] : EB[s23 >> 1];
        census_pair<CM>(na01, nb01, ac01, bc01, m01[j], acc01);
        census_pair<CM>(na23, nb23, ac23, bc23, m23[j], acc23);
    }
}

// ---------------------------------------------------------------------------
// Kernel 2: census-SAD over half-space offsets (dh>0, or dh==0 && dw>0);
// each unordered pair counted once, doubled in finalize.
// ---------------------------------------------------------------------------
template<bool CM>
__device__ __forceinline__ float census_block(
    const float (&As)[TH][TW], const float (&A1)[TH][TW],
    const float (&Bs)[TH][TW], const float (&B1)[TH][TW],
    int gx, int gy, int ty, int cb)
{
    float2 ac01 = *(const float2*)&As[ty][cb + RAD];
    float2 ac23 = *(const float2*)&As[ty][cb + RAD + 2];
    float2 bc01 = *(const float2*)&Bs[ty][cb + RAD];
    float2 bc23 = *(const float2*)&Bs[ty][cb + RAD + 2];

    float2 m01[9], m23[9];
    if (CM) {
#pragma unroll
        for (int j = 0; j < 9; j++) {
            int dw = j - 4;
            m01[j].x = ((unsigned)(gx + dw)     < WW) ? 1.f : 0.f;
            m01[j].y = ((unsigned)(gx + 1 + dw) < WW) ? 1.f : 0.f;
            m23[j].x = ((unsigned)(gx + 2 + dw) < WW) ? 1.f : 0.f;
            m23[j].y = ((unsigned)(gx + 3 + dw) < WW) ? 1.f : 0.f;
        }
    }

    float2 acc01 = {0.f, 0.f}, acc23 = {0.f, 0.f};

    // dh = 0 (same row), dw = 1..4  => j = 5..8
    row_accum<5, CM>(As[ty], A1[ty], Bs[ty], B1[ty], cb,
                     ac01, ac23, bc01, bc23, m01, m23, acc01, acc23);

    int dhmax = HH - 1 - gy; if (dhmax > RAD) dhmax = RAD;
#pragma unroll 1
    for (int dh = 1; dh <= dhmax; dh++) {
        row_accum<0, CM>(As[ty+dh], A1[ty+dh], Bs[ty+dh], B1[ty+dh], cb,
                         ac01, ac23, bc01, bc23, m01, m23, acc01, acc23);
    }
    return (acc01.x + acc01.y) + (acc23.x + acc23.y);
}

__global__ __launch_bounds__(NTHREADS)
void census_kernel(const float* __restrict__ a_g,   // pattern_proj
                   const float* __restrict__ b_g)   // im
{
    __shared__ __align__(16) float As[TH][TW];
    __shared__ __align__(16) float A1[TH][TW];   // shifted: A1[r][c] = As[r][c+1]
    __shared__ __align__(16) float Bs[TH][TW];
    __shared__ __align__(16) float B1[TH][TW];

    int x0 = blockIdx.x * TILE_W;
    int y0 = blockIdx.y * BYT;
    const float* ap = a_g + (size_t)blockIdx.z * (HH * WW);
    const float* bp = b_g + (size_t)blockIdx.z * (HH * WW);
    int tid = threadIdx.y * BXT + threadIdx.x;

    for (int i = tid; i < TH * TW; i += NTHREADS) {
        int r = i / TW, c = i - r * TW;
        int gy = y0 + r;
        int gx = x0 + c - RAD;
        float av = 0.f, bv = 0.f;
        if (gy < HH && (unsigned)gx < WW) {
            int g = gy * WW + gx;
            av = ap[g];
            bv = bp[g];
        }
        As[r][c] = av;
        Bs[r][c] = bv;
        if (c) { A1[r][c-1] = av; B1[r][c-1] = bv; }
        // A1[r][TW-1], B1[r][TW-1] stay garbage: loaded into regs but never used
    }
    __syncthreads();

    int tx = threadIdx.x, ty = threadIdx.y;
    int cb = PX * tx;            // halo col base of this thread's 12-float segment
    int gx = x0 + cb;            // first of 4 pixels
    int gy = y0 + ty;

    bool cm = (blockIdx.x == 0) || (blockIdx.x == gridDim.x - 1);
    float acc = cm ? census_block<true >(As, A1, Bs, B1, gx, gy, ty, cb)
                   : census_block<false>(As, A1, Bs, B1, gx, gy, ty, cb);

    // block reduce -> one double atomic per block
#pragma unroll
    for (int o = 16; o > 0; o >>= 1)
        acc += __shfl_down_sync(0xffffffffu, acc, o);

    __shared__ float warpsum[NTHREADS / 32];
    if ((tid & 31) == 0) warpsum[tid >> 5] = acc;
    __syncthreads();
    if (tid < (NTHREADS / 32)) {
        float s = warpsum[tid];
#pragma unroll
        for (int o = (NTHREADS / 64); o > 0; o >>= 1)
            s += __shfl_down_sync(0xffffffffu, s, o);
        if (tid == 0) atomicAdd(&g_acc, (double)s);
    }
}

// ---------------------------------------------------------------------------
// Kernel 3: val = 2 * g_acc / (81 * B*H*W)
// ---------------------------------------------------------------------------
__global__ void finalize_kernel(float* __restrict__ out, int lead, double inv_norm)
{
    float v = (float)(2.0 * g_acc * inv_norm);
    for (int i = threadIdx.x; i < lead; i += 32) out[i] = v;
}

extern "C" void kernel_launch(void* const* d_in, const int* in_sizes, int n_in,
                              void* d_out, int out_size)
{
    const float* disp    = (const float*)d_in[0];
    const float* im      = (const float*)d_in[1];
    const float* pattern = (const float*)d_in[2];
    float* out = (float*)d_out;

    int total = in_sizes[0];           // B*1*H*W
    int B = total / (HH * WW);
    int lead = out_size - total;       // scalar(s) precede pattern_proj
    float* proj = out + lead;

    proj_kernel<<<(total + 255) / 256, 256>>>(disp, pattern, proj, total);

    dim3 grid(WW / TILE_W, HH / BYT, B);   // 5 x 64 x B
    dim3 blk(BXT, BYT);
    census_kernel<<<grid, blk>>>(proj, im);

    finalize_kernel<<<1, 32>>>(out, lead, 1.0 / (81.0 * (double)total));
}